// round 1
// baseline (speedup 1.0000x reference)
#include <cuda_runtime.h>
#include <cuda_bf16.h>

// Problem constants (shapes fixed by setup_inputs): bs=16, nq=900, nc=91, T=1600
#define NC     91
#define NMAX   14400
#define NTILE  16
#define TTILE  160

// Scratch: class-cost table cc2[n][c] = 2*(pos-neg) + 2   (5.24 MB)
__device__ float g_cc[NMAX * NC];

// ---------------------------------------------------------------------------
// Kernel 1: per-(query, class) focal classification cost.
//   p = sigmoid(x);  let s = 1+e^x, r = 1/s = (1-p), ls = log s = -log(1-p)
//   log p = x - ls
//   pos = 0.25*(1-p)^2*(-log p) = 0.25*r*r*(ls - x)
//   neg = 0.75*p^2*(-log(1-p)) = 0.75*p*p*ls
//   stored value folds COST_CLASS=2 and the "+2" constant from -2*giou's (-(-1)):
//   cc2 = 2*(pos-neg) + 2
// eps=1e-8 omitted: |logits| ~ N(0,1) so p in [~2e-3, 1-2e-3]; error < 1e-5 abs.
// ---------------------------------------------------------------------------
__global__ void class_cost_kernel(const float* __restrict__ logits, int total)
{
    int i = blockIdx.x * blockDim.x + threadIdx.x;
    if (i >= total) return;
    float x  = logits[i];
    float ex = __expf(x);
    float s  = 1.0f + ex;
    float r  = __frcp_rn(s);     // = 1 - p
    float ls = __logf(s);        // = -log(1-p)
    float p  = 1.0f - r;
    float pos = 0.25f * r * r * (ls - x);
    float neg = 0.75f * p * p * ls;
    g_cc[i] = 2.0f * (pos - neg) + 2.0f;
}

// ---------------------------------------------------------------------------
// Kernel 2: main N x T cost matrix.
// Block: TTILE threads (one target each), NTILE queries per block.
// Shared: class-cost slice [NTILE x NC], per-query cxcywh/xyxy/area.
// ---------------------------------------------------------------------------
__global__ __launch_bounds__(TTILE)
void cost_matrix_kernel(const float* __restrict__ pred_boxes,  // [N,4] cxcywh
                        const int*   __restrict__ tgt_ids,     // [T]
                        const float* __restrict__ tgt_bbox,    // [T,4] cxcywh
                        float*       __restrict__ out,         // [N,T]
                        int N, int T)
{
    __shared__ float  s_cc[NTILE * NC];
    __shared__ float4 s_box[NTILE];    // cxcywh
    __shared__ float4 s_xyxy[NTILE];
    __shared__ float  s_area[NTILE];

    const int n0 = blockIdx.y * NTILE;
    const int t  = blockIdx.x * TTILE + threadIdx.x;

    // Stage class-cost slice for this block's 16 queries
    for (int i = threadIdx.x; i < NTILE * NC; i += TTILE)
        s_cc[i] = g_cc[n0 * NC + i];

    if (threadIdx.x < NTILE) {
        int n = n0 + threadIdx.x;
        float4 b = __ldg(((const float4*)pred_boxes) + n);
        s_box[threadIdx.x] = b;
        float hw = 0.5f * b.z, hh = 0.5f * b.w;
        s_xyxy[threadIdx.x] = make_float4(b.x - hw, b.y - hh, b.x + hw, b.y + hh);
        s_area[threadIdx.x] = b.z * b.w;
    }
    __syncthreads();

    if (t >= T) return;

    // Per-target data (registers)
    const float4 tb  = __ldg(((const float4*)tgt_bbox) + t);
    const int tcls   = tgt_ids[t];
    const float thw = 0.5f * tb.z, thh = 0.5f * tb.w;
    const float tx0 = tb.x - thw, ty0 = tb.y - thh;
    const float tx1 = tb.x + thw, ty1 = tb.y + thh;
    const float ta  = tb.z * tb.w;

    float* op = out + (size_t)n0 * T + t;

    #pragma unroll
    for (int i = 0; i < NTILE; i++) {
        const float4 nb = s_box[i];
        const float4 nx = s_xyxy[i];
        const float  na = s_area[i];
        const float  cc = s_cc[i * NC + tcls];

        // L1 on cxcywh
        float l1 = fabsf(nb.x - tb.x) + fabsf(nb.y - tb.y)
                 + fabsf(nb.z - tb.z) + fabsf(nb.w - tb.w);

        // intersection
        float ix0 = fmaxf(nx.x, tx0), iy0 = fmaxf(nx.y, ty0);
        float ix1 = fminf(nx.z, tx1), iy1 = fminf(nx.w, ty1);
        float iw  = fmaxf(ix1 - ix0, 0.0f);
        float ih  = fmaxf(iy1 - iy0, 0.0f);
        float inter = iw * ih;
        float uni   = na + ta - inter;

        // enclosing box (always non-degenerate: max >= min)
        float ex0 = fminf(nx.x, tx0), ey0 = fminf(nx.y, ty0);
        float ex1 = fmaxf(nx.z, tx1), ey1 = fmaxf(nx.w, ty1);
        float ae  = (ex1 - ex0) * (ey1 - ey0);

        float iou = __fdividef(inter, uni);
        float q   = __fdividef(uni, ae);

        // C = 5*l1 + [2*(pos-neg)+2] - 2*(iou + uni/ae)
        float c = fmaf(5.0f, l1, cc);
        c = fmaf(-2.0f, iou + q, c);

        op[(size_t)i * T] = c;
    }
}

extern "C" void kernel_launch(void* const* d_in, const int* in_sizes, int n_in,
                              void* d_out, int out_size)
{
    const float* pred_logits = (const float*)d_in[0];   // [bs, nq, nc]
    const float* pred_boxes  = (const float*)d_in[1];   // [bs, nq, 4]
    const int*   tgt_ids     = (const int*)  d_in[2];   // [T]
    const float* tgt_bbox    = (const float*)d_in[3];   // [T, 4]
    float*       out         = (float*)d_out;           // [N, T]

    const int N = in_sizes[1] / 4;       // 14400
    const int T = in_sizes[2];           // 1600
    const int NCls = in_sizes[0] / N;    // 91

    // Kernel 1: class cost table
    {
        int total = N * NCls;
        int threads = 256;
        class_cost_kernel<<<(total + threads - 1) / threads, threads>>>(pred_logits, total);
    }

    // Kernel 2: main cost matrix
    {
        dim3 grid((T + TTILE - 1) / TTILE, (N + NTILE - 1) / NTILE);
        cost_matrix_kernel<<<grid, TTILE>>>(pred_boxes, tgt_ids, tgt_bbox, out, N, T);
    }
}

// round 2
// speedup vs baseline: 1.2670x; 1.2670x over previous
#include <cuda_runtime.h>
#include <cuda_bf16.h>

// Shapes fixed by setup_inputs: bs=16, nq=900, nc=91, T=1600  ->  N=14400
#define NC     91
#define NMAX   14400
#define NTILE  16
#define TTILE  160          // threads per block
#define TPB    (2*TTILE)    // targets per block (2 adjacent per thread)

// Scratch: class-cost table cc2[n][c] = 2*(pos-neg) + 2   (5.24 MB)
__device__ float g_cc[NMAX * NC];

// ---------------------------------------------------------------------------
// Kernel 1: per-(query, class) focal classification cost, float4-vectorized.
//   p = sigmoid(x);  s = 1+e^x, r = 1/s = 1-p, ls = log s = -log(1-p)
//   pos = 0.25*r*r*(ls - x);  neg = 0.75*p*p*ls
//   stored: cc2 = 2*(pos-neg) + 2   (folds COST_CLASS=2 and giou's +1)
// eps=1e-8 omitted: logits ~ N(0,1), abs error < 1e-5.
// ---------------------------------------------------------------------------
__device__ __forceinline__ float focal_cc(float x)
{
    float ex = __expf(x);
    float s  = 1.0f + ex;
    float r  = __frcp_rn(s);     // 1 - p
    float ls = __logf(s);        // -log(1-p)
    float p  = 1.0f - r;
    float pos = 0.25f * r * r * (ls - x);
    float neg = 0.75f * p * p * ls;
    return 2.0f * (pos - neg) + 2.0f;
}

__global__ void class_cost_kernel(const float4* __restrict__ logits4, int total4)
{
    int i = blockIdx.x * blockDim.x + threadIdx.x;
    if (i >= total4) return;
    float4 x = logits4[i];
    float4 o;
    o.x = focal_cc(x.x);
    o.y = focal_cc(x.y);
    o.z = focal_cc(x.z);
    o.w = focal_cc(x.w);
    ((float4*)g_cc)[i] = o;
}

// ---------------------------------------------------------------------------
// Kernel 2: main N x T cost matrix. Each thread owns 2 adjacent targets,
// iterates over NTILE queries staged in shared memory.
// ---------------------------------------------------------------------------
struct Tgt {
    float cx, cy, w, h;          // cxcywh
    float x0, y0, x1, y1;        // xyxy
    float area;
    float cc;                    // gathered class cost (set per query iter)
};

__device__ __forceinline__ float cost_one(const float4 nb, const float4 nx,
                                          const float na, const float cc,
                                          const Tgt& t)
{
    // L1 on cxcywh (abs folds into FADD operand modifiers)
    float l1 = (fabsf(nb.x - t.cx) + fabsf(nb.y - t.cy))
             + (fabsf(nb.z - t.w)  + fabsf(nb.w - t.h));

    // intersection
    float iw = fmaxf(fminf(nx.z, t.x1) - fmaxf(nx.x, t.x0), 0.0f);
    float ih = fmaxf(fminf(nx.w, t.y1) - fmaxf(nx.y, t.y0), 0.0f);
    float inter = iw * ih;
    float uni   = na + t.area - inter;

    // enclosing box
    float ew = fmaxf(nx.z, t.x1) - fminf(nx.x, t.x0);
    float eh = fmaxf(nx.w, t.y1) - fminf(nx.y, t.y0);
    float ae = ew * eh;

    // iou + uni/ae = (inter*ae + uni^2) / (uni*ae)   -- single rcp
    float num  = fmaf(uni, uni, inter * ae);
    float term = __fdividef(num, uni * ae);

    // C = 5*l1 + cc - 2*(iou + uni/ae)
    return fmaf(-2.0f, term, fmaf(5.0f, l1, cc));
}

__global__ __launch_bounds__(TTILE)
void cost_matrix_kernel(const float* __restrict__ pred_boxes,  // [N,4] cxcywh
                        const int*   __restrict__ tgt_ids,     // [T]
                        const float* __restrict__ tgt_bbox,    // [T,4] cxcywh
                        float*       __restrict__ out,         // [N,T]
                        int N, int T)
{
    __shared__ float  s_cc[NTILE * NC];
    __shared__ float4 s_box[NTILE];    // cxcywh
    __shared__ float4 s_xyxy[NTILE];
    __shared__ float  s_area[NTILE];

    const int n0 = blockIdx.y * NTILE;
    const int t0 = blockIdx.x * TPB + 2 * threadIdx.x;

    // Stage class-cost slice for this block's 16 queries
    for (int i = threadIdx.x; i < NTILE * NC; i += TTILE)
        s_cc[i] = g_cc[n0 * NC + i];

    if (threadIdx.x < NTILE) {
        int n = n0 + threadIdx.x;
        float4 b = __ldg(((const float4*)pred_boxes) + n);
        s_box[threadIdx.x] = b;
        float hw = 0.5f * b.z, hh = 0.5f * b.w;
        s_xyxy[threadIdx.x] = make_float4(b.x - hw, b.y - hh, b.x + hw, b.y + hh);
        s_area[threadIdx.x] = b.z * b.w;
    }
    __syncthreads();

    if (t0 + 1 >= T) return;

    // Two targets in registers
    Tgt A, B;
    {
        float4 ta = __ldg(((const float4*)tgt_bbox) + t0);
        float4 tb = __ldg(((const float4*)tgt_bbox) + t0 + 1);
        A.cx = ta.x; A.cy = ta.y; A.w = ta.z; A.h = ta.w;
        B.cx = tb.x; B.cy = tb.y; B.w = tb.z; B.h = tb.w;
        float ahw = 0.5f * ta.z, ahh = 0.5f * ta.w;
        float bhw = 0.5f * tb.z, bhh = 0.5f * tb.w;
        A.x0 = ta.x - ahw; A.y0 = ta.y - ahh; A.x1 = ta.x + ahw; A.y1 = ta.y + ahh;
        B.x0 = tb.x - bhw; B.y0 = tb.y - bhh; B.x1 = tb.x + bhw; B.y1 = tb.y + bhh;
        A.area = ta.z * ta.w;
        B.area = tb.z * tb.w;
    }
    const int clsA = tgt_ids[t0];
    const int clsB = tgt_ids[t0 + 1];

    float* op = out + (size_t)n0 * T + t0;

    #pragma unroll
    for (int i = 0; i < NTILE; i++) {
        const float4 nb = s_box[i];
        const float4 nx = s_xyxy[i];
        const float  na = s_area[i];
        const float  ccA = s_cc[i * NC + clsA];
        const float  ccB = s_cc[i * NC + clsB];

        float cA = cost_one(nb, nx, na, ccA, A);
        float cB = cost_one(nb, nx, na, ccB, B);

        *(float2*)(op + (size_t)i * T) = make_float2(cA, cB);
    }
}

extern "C" void kernel_launch(void* const* d_in, const int* in_sizes, int n_in,
                              void* d_out, int out_size)
{
    const float* pred_logits = (const float*)d_in[0];   // [bs, nq, nc]
    const float* pred_boxes  = (const float*)d_in[1];   // [bs, nq, 4]
    const int*   tgt_ids     = (const int*)  d_in[2];   // [T]
    const float* tgt_bbox    = (const float*)d_in[3];   // [T, 4]
    float*       out         = (float*)d_out;           // [N, T]

    const int N = in_sizes[1] / 4;       // 14400
    const int T = in_sizes[2];           // 1600

    // Kernel 1: class cost table (total = N*91 = 1,310,400, divisible by 4)
    {
        int total4 = (N * NC) / 4;
        int threads = 256;
        class_cost_kernel<<<(total4 + threads - 1) / threads, threads>>>(
            (const float4*)pred_logits, total4);
    }

    // Kernel 2: main cost matrix
    {
        dim3 grid(T / TPB, (N + NTILE - 1) / NTILE);   // 5 x 900
        cost_matrix_kernel<<<grid, TTILE>>>(pred_boxes, tgt_ids, tgt_bbox, out, N, T);
    }
}